// round 6
// baseline (speedup 1.0000x reference)
#include <cuda_runtime.h>
#include <math.h>

#define BS   32
#define NV   6
#define MF   12
#define MT   16
#define NF   1992
#define NR   11
#define HID  128
#define RED  256
#define OUTD 90

#define NBV   (BS*NV)        // 192
#define NBVM  (BS*NV*MF)     // 2304
#define NF4   (NF/4)         // 498
#define I4TOT (MT*NF4)       // 7968 float4 per (b,v,m)
#define TOT4  (NBVM*I4TOT)   // 18,358,272 float4 total
#define CAP2  512            // nonzeros per (b,v,m); mean ~32 => hugely safe

#define TILE  16
#define NPRE  126            // 125 emb-tile blocks + 1 edge block
#define ROLE0 (NBV + NPRE)   // 318: first compact block
#define NCOMPACT 2048
#define GRID1 (ROLE0 + NCOMPACT)

// ---------------- device scratch (no allocations; zero-init for first run; ----
// ---------------- final_kernel re-zeroes mutable state for graph replays) -----
__device__ float  g_red_emb[NF*RED];     // 2.04 MB node table (L2-resident)
__device__ float  g_red_edge[NR*RED];
__device__ float  g_attn[NBVM];
__device__ float  g_fsum[NBVM];
__device__ int    g_cnt[NBVM];           // per-(b,v,m) nonzero counters
__device__ float2 g_list[NBVM*CAP2];     // {bitcast(n*RED), value}
__device__ float  g_hg[BS*RED];          // h.sum(v,m)
__device__ float  g_hp[BS*RED];          // fsum-weighted h sum

// ---------------- fused kernel 1: attn | precompute | compact (independent) ---
__device__ __forceinline__ void push_nz(float4 v, int i) {
    if (v.x != 0.f || v.y != 0.f || v.z != 0.f || v.w != 0.f) {
        const int bvm  = i / I4TOT;
        const int rem4 = i - bvm * I4TOT;
        const int n0   = (rem4 % NF4) * (4*RED);   // pre-scaled row offset
        float2* lst = g_list + bvm * CAP2;
        if (v.x != 0.f) { int p = atomicAdd(&g_cnt[bvm],1); if (p < CAP2) lst[p] = make_float2(__int_as_float(n0        ), v.x); }
        if (v.y != 0.f) { int p = atomicAdd(&g_cnt[bvm],1); if (p < CAP2) lst[p] = make_float2(__int_as_float(n0 +   RED), v.y); }
        if (v.z != 0.f) { int p = atomicAdd(&g_cnt[bvm],1); if (p < CAP2) lst[p] = make_float2(__int_as_float(n0 + 2*RED), v.z); }
        if (v.w != 0.f) { int p = atomicAdd(&g_cnt[bvm],1); if (p < CAP2) lst[p] = make_float2(__int_as_float(n0 + 3*RED), v.w); }
    }
}

__global__ void __launch_bounds__(256) fused_kernel(
        const float* __restrict__ feat,  const float* __restrict__ neigh,
        const float* __restrict__ emb,   const float* __restrict__ W_v,
        const float* __restrict__ b_v,   const float* __restrict__ W_edge,
        const float* __restrict__ W_r,   const float* __restrict__ b_r,
        const float* __restrict__ W_alpha, const float* __restrict__ b_alpha,
        const float* __restrict__ W_beta,  const float* __restrict__ b_beta) {
    __shared__ float4 s_a[TILE][HID/4];            // 8 KB (precompute); reused views below
    float* s_dot = (float*)&s_a[0][0];             // [MF]
    float* s_fs  = (float*)&s_a[1][0];             // [MF]

    const int bid = blockIdx.x;
    const int tid = threadIdx.x;

    if (bid < NBV) {
        // ---------------- role A: per-(b,v) attention + feat row sums ----------
        const int bv   = bid;
        const int warp = tid >> 5;
        const int lane = tid & 31;

        for (int m = warp; m < MF; m += 8) {
            const float4* fp = (const float4*)(feat + ((size_t)bv * MF + m) * NF);
            const float4* wa = (const float4*)W_alpha;
            float d0=0.f,d1=0.f,d2=0.f,d3=0.f, f0=0.f,f1=0.f,f2=0.f,f3=0.f;
            int i = lane;
            for (; i + 96 < NF4; i += 128) {
                float4 a0 = __ldcs(fp + i);
                float4 a1 = __ldcs(fp + i + 32);
                float4 a2 = __ldcs(fp + i + 64);
                float4 a3 = __ldcs(fp + i + 96);
                float4 w0 = __ldg(wa + i);
                float4 w1 = __ldg(wa + i + 32);
                float4 w2 = __ldg(wa + i + 64);
                float4 w3 = __ldg(wa + i + 96);
                d0 += a0.x*w0.x + a0.y*w0.y + a0.z*w0.z + a0.w*w0.w;
                d1 += a1.x*w1.x + a1.y*w1.y + a1.z*w1.z + a1.w*w1.w;
                d2 += a2.x*w2.x + a2.y*w2.y + a2.z*w2.z + a2.w*w2.w;
                d3 += a3.x*w3.x + a3.y*w3.y + a3.z*w3.z + a3.w*w3.w;
                f0 += a0.x + a0.y + a0.z + a0.w;
                f1 += a1.x + a1.y + a1.z + a1.w;
                f2 += a2.x + a2.y + a2.z + a2.w;
                f3 += a3.x + a3.y + a3.z + a3.w;
            }
            for (; i < NF4; i += 32) {
                float4 a = __ldcs(fp + i);
                float4 w = __ldg(wa + i);
                d0 += a.x*w.x + a.y*w.y + a.z*w.z + a.w*w.w;
                f0 += a.x + a.y + a.z + a.w;
            }
            float dot = (d0 + d1) + (d2 + d3);
            float fs  = (f0 + f1) + (f2 + f3);
            #pragma unroll
            for (int o = 16; o > 0; o >>= 1) {
                dot += __shfl_down_sync(0xffffffffu, dot, o);
                fs  += __shfl_down_sync(0xffffffffu, fs,  o);
            }
            if (lane == 0) { s_dot[m] = dot; s_fs[m] = fs; }
        }
        __syncthreads();

        if (tid == 0) {
            const int v = bv % NV;
            float lg[MF];
            float mx = -1e30f;
            #pragma unroll
            for (int m = 0; m < MF; m++) {
                lg[m] = s_dot[m] + __ldg(&b_alpha[m]);
                mx = fmaxf(mx, lg[m]);
            }
            float sum = 0.f;
            #pragma unroll
            for (int m = 0; m < MF; m++) { lg[m] = expf(lg[m] - mx); sum += lg[m]; }
            const float inv = 1.f / sum;
            float bl = __ldg(&b_beta[v]);
            #pragma unroll
            for (int m = 0; m < MF; m++) { lg[m] *= inv; bl += __ldg(&W_beta[m]) * lg[m]; }
            const float lamb = expf(-0.1f * (float)(NV - v));   // GAMMA=0.1
            const float beta = tanhf(bl) * lamb;
            #pragma unroll
            for (int m = 0; m < MF; m++) {
                g_attn[bv*MF + m] = lg[m] * beta;
                g_fsum[bv*MF + m] = s_fs[m];
            }
        }
    } else if (bid < ROLE0) {
        // ---------------- role B: reduced node/edge tables (tiled GEMM) --------
        const int pb = bid - NBV;
        const int r  = tid;

        const float* src; const float* Wp; const float* bp; float* outp;
        int row0, nrow;
        if (pb < 125) {
            row0 = pb * TILE; nrow = min(TILE, NF - row0);
            src = emb; Wp = W_v; bp = b_v; outp = g_red_emb;
        } else {
            row0 = 0; nrow = NR;
            src = W_edge; Wp = W_r; bp = b_r; outp = g_red_edge;
        }

        for (int idx = r; idx < nrow * (HID/4); idx += 256) {
            int t = idx >> 5, k = idx & 31;
            s_a[t][k] = ((const float4*)(src + (size_t)(row0 + t) * HID))[k];
        }
        __syncthreads();

        float acc[TILE];
        #pragma unroll
        for (int t = 0; t < TILE; t++) acc[t] = 0.f;

        const float4* w4 = (const float4*)(Wp + (size_t)r * HID);
        #pragma unroll 8
        for (int k = 0; k < HID/4; k++) {
            float4 w = __ldg(&w4[k]);
            #pragma unroll
            for (int t = 0; t < TILE; t++) {
                float4 a = s_a[t][k];
                acc[t] += a.x*w.x + a.y*w.y + a.z*w.z + a.w*w.w;
            }
        }
        const float bias = __ldg(&bp[r]);
        for (int t = 0; t < nrow; t++)
            outp[(row0 + t) * RED + r] = acc[t] + bias;
    } else {
        // ---------------- role C: 293 MB stream -> sparse compaction -----------
        const float4* np = (const float4*)neigh;
        const int stride = (GRID1 - ROLE0) * 256;
        int i = (bid - ROLE0) * 256 + tid;
        for (; i + 7*stride < TOT4; i += 8*stride) {
            float4 v0 = __ldcs(np + i);
            float4 v1 = __ldcs(np + i + 1*stride);
            float4 v2 = __ldcs(np + i + 2*stride);
            float4 v3 = __ldcs(np + i + 3*stride);
            float4 v4 = __ldcs(np + i + 4*stride);
            float4 v5 = __ldcs(np + i + 5*stride);
            float4 v6 = __ldcs(np + i + 6*stride);
            float4 v7 = __ldcs(np + i + 7*stride);
            push_nz(v0, i);
            push_nz(v1, i + 1*stride);
            push_nz(v2, i + 2*stride);
            push_nz(v3, i + 3*stride);
            push_nz(v4, i + 4*stride);
            push_nz(v5, i + 5*stride);
            push_nz(v6, i + 6*stride);
            push_nz(v7, i + 7*stride);
        }
        for (; i < TOT4; i += stride)
            push_nz(__ldcs(np + i), i);
    }
}

// ---------------- kernel 2: expansion, one block per (b,v) handling 12 m ------
// grid = 192, block = 256 (thread r owns reduced-dim column r)
__global__ void __launch_bounds__(256) expand_kernel(const float* __restrict__ rel,
                                                     const float* __restrict__ W_l,
                                                     const float* __restrict__ b_l) {
    __shared__ float s_edge[MF][NR];   // per-m edge sums over t
    __shared__ float s_attn[MF];
    __shared__ float s_fs[MF];
    __shared__ int   s_cnt[MF];

    const int bv  = blockIdx.x;
    const int r   = threadIdx.x;

    // cooperative edge aggregation: 132 (m,e) pairs, each sums 16 strided values
    if (r < MF*NR) {
        const int m = r / NR, e = r - m * NR;
        const float* rp = rel + ((size_t)(bv*MF + m) * MT) * NR + e;
        float s = 0.f;
        #pragma unroll
        for (int t = 0; t < MT; t++) s += __ldg(rp + t*NR);
        s_edge[m][e] = s;
    }
    if (r >= 224 && r < 224 + MF) {          // separate warp: per-m scalars
        const int m = r - 224;
        s_attn[m] = g_attn[bv*MF + m];
        s_fs[m]   = g_fsum[bv*MF + m];
        s_cnt[m]  = min(g_cnt[bv*MF + m], CAP2);
    }
    __syncthreads();

    // hoist edge table column r into registers (reused for all 12 m)
    float er[NR];
    #pragma unroll
    for (int e = 0; e < NR; e++) er[e] = __ldg(&g_red_edge[e*RED + r]);
    const float wl = __ldg(&W_l[r*RED + r]);
    const float bl = __ldg(&b_l[r]);
    const float* table = g_red_emb + r;       // entries store pre-scaled n*RED

    float hg = 0.f, hp = 0.f;
    #pragma unroll 1
    for (int m = 0; m < MF; m++) {
        const float2* lst = g_list + (bv*MF + m) * CAP2;
        const int cnt = s_cnt[m];
        float acc = 0.f;
        int j = 0;
        for (; j + 8 <= cnt; j += 8) {
            float2 e0 = __ldg(lst+j),   e1 = __ldg(lst+j+1), e2 = __ldg(lst+j+2), e3 = __ldg(lst+j+3);
            float2 e4 = __ldg(lst+j+4), e5 = __ldg(lst+j+5), e6 = __ldg(lst+j+6), e7 = __ldg(lst+j+7);
            float a0 = __ldg(table + __float_as_int(e0.x));
            float a1 = __ldg(table + __float_as_int(e1.x));
            float a2 = __ldg(table + __float_as_int(e2.x));
            float a3 = __ldg(table + __float_as_int(e3.x));
            float a4 = __ldg(table + __float_as_int(e4.x));
            float a5 = __ldg(table + __float_as_int(e5.x));
            float a6 = __ldg(table + __float_as_int(e6.x));
            float a7 = __ldg(table + __float_as_int(e7.x));
            acc += e0.y*a0 + e1.y*a1 + e2.y*a2 + e3.y*a3
                 + e4.y*a4 + e5.y*a5 + e6.y*a6 + e7.y*a7;
        }
        for (; j < cnt; j++) {
            float2 e0 = __ldg(lst+j);
            acc += e0.y * __ldg(table + __float_as_int(e0.x));
        }
        float edge = 0.f;
        #pragma unroll
        for (int e = 0; e < NR; e++) edge += s_edge[m][e] * er[e];
        float h = fmaxf(wl * (s_attn[m]*acc + edge) + bl, 0.f);
        hg += h;
        hp += s_fs[m] * h;
    }

    const int b = bv / NV;
    atomicAdd(&g_hg[b*RED + r], hg);
    atomicAdd(&g_hp[b*RED + r], hp);
}

// ---------------- kernel 3: FC + sigmoid + state reset for next replay --------
// grid = 32 (batch), block = 256
__global__ void final_kernel(const float* __restrict__ fc_W,
                             const float* __restrict__ fc_b,
                             float* __restrict__ out) {
    __shared__ float z[2*RED];
    const int b = blockIdx.x;
    const int r = threadIdx.x;

    z[r]       = g_hg[b*RED + r];
    z[RED + r] = g_hp[b*RED + r];
    // reset mutable state so the next graph replay starts clean
    g_hg[b*RED + r] = 0.f;
    g_hp[b*RED + r] = 0.f;
    {
        int gid = b * 256 + r;                 // 8192 threads cover 2304 counters
        if (gid < NBVM) g_cnt[gid] = 0;
    }
    __syncthreads();

    if (r < OUTD) {
        const float* w = fc_W + r * (2*RED);
        float a0 = 0.f, a1 = 0.f, a2 = 0.f, a3 = 0.f;
        #pragma unroll 4
        for (int k = 0; k < 2*RED; k += 4) {
            a0 += z[k]   * __ldg(&w[k]);
            a1 += z[k+1] * __ldg(&w[k+1]);
            a2 += z[k+2] * __ldg(&w[k+2]);
            a3 += z[k+3] * __ldg(&w[k+3]);
        }
        float acc = __ldg(&fc_b[r]) + ((a0 + a1) + (a2 + a3));
        out[b*OUTD + r] = 1.f / (1.f + expf(-acc));
    }
}

// ---------------- launcher ----------------
extern "C" void kernel_launch(void* const* d_in, const int* in_sizes, int n_in,
                              void* d_out, int out_size) {
    const float* feat    = (const float*)d_in[0];
    const float* neigh   = (const float*)d_in[1];
    const float* rel     = (const float*)d_in[2];
    const float* emb     = (const float*)d_in[3];
    const float* W_edge  = (const float*)d_in[4];
    const float* W_v     = (const float*)d_in[5];
    const float* W_r     = (const float*)d_in[6];
    const float* b_v     = (const float*)d_in[7];
    const float* b_r     = (const float*)d_in[8];
    const float* W_alpha = (const float*)d_in[9];
    const float* b_alpha = (const float*)d_in[10];
    const float* W_beta  = (const float*)d_in[11];
    const float* b_beta  = (const float*)d_in[12];
    const float* W_l     = (const float*)d_in[13];
    const float* b_l     = (const float*)d_in[14];
    const float* fc_W    = (const float*)d_in[15];
    const float* fc_b    = (const float*)d_in[16];
    float* out = (float*)d_out;

    fused_kernel<<<GRID1, 256>>>(feat, neigh, emb, W_v, b_v, W_edge, W_r, b_r,
                                 W_alpha, b_alpha, W_beta, b_beta);
    expand_kernel<<<NBV, 256>>>(rel, W_l, b_l);
    final_kernel<<<BS, RED>>>(fc_W, fc_b, out);
}

// round 8
// speedup vs baseline: 1.6294x; 1.6294x over previous
#include <cuda_runtime.h>
#include <math.h>

#define BS   32
#define NV   6
#define MF   12
#define MT   16
#define NF   1992
#define NR   11
#define HID  128
#define RED  256
#define OUTD 90

#define NBV   (BS*NV)        // 192
#define NBVM  (BS*NV*MF)     // 2304
#define NF4   (NF/4)         // 498
#define I4TOT (MT*NF4)       // 7968 float4 per (b,v,m)
#define TOT4  (NBVM*I4TOT)   // 18,358,272 float4 total
#define CAP2  512            // nonzeros per (b,v,m); mean ~32 => hugely safe

#define TILE  16
#define NPRE  126            // 125 emb-tile blocks + 1 edge block
#define ROLE0 (NBV + NPRE)   // 318: first compact block
#define NCOMPACT 2048
#define GRID1 (ROLE0 + NCOMPACT)

// ---------------- device scratch (no allocations; zero-init for first run; ----
// ---------------- final_kernel re-zeroes mutable state for graph replays) -----
__device__ float  g_red_emb[NF*RED];     // 2.04 MB node table (L2-resident)
__device__ float  g_red_edge[NR*RED];
__device__ float  g_attn[NBVM];
__device__ float  g_fsum[NBVM];
__device__ int    g_cnt[NBVM];           // per-(b,v,m) nonzero counters
__device__ float2 g_list[NBVM*CAP2];     // {bitcast(n*RED), value}
__device__ float  g_hg[BS*RED];          // h.sum(v,m)
__device__ float  g_hp[BS*RED];          // fsum-weighted h sum

// ---------------- fused kernel 1: attn | precompute | compact (independent) ---
__device__ __forceinline__ void push_nz(float4 v, int i) {
    if (v.x != 0.f || v.y != 0.f || v.z != 0.f || v.w != 0.f) {
        const int bvm  = i / I4TOT;
        const int rem4 = i - bvm * I4TOT;
        const int n0   = (rem4 % NF4) * (4*RED);   // pre-scaled row offset
        float2* lst = g_list + bvm * CAP2;
        if (v.x != 0.f) { int p = atomicAdd(&g_cnt[bvm],1); if (p < CAP2) lst[p] = make_float2(__int_as_float(n0        ), v.x); }
        if (v.y != 0.f) { int p = atomicAdd(&g_cnt[bvm],1); if (p < CAP2) lst[p] = make_float2(__int_as_float(n0 +   RED), v.y); }
        if (v.z != 0.f) { int p = atomicAdd(&g_cnt[bvm],1); if (p < CAP2) lst[p] = make_float2(__int_as_float(n0 + 2*RED), v.z); }
        if (v.w != 0.f) { int p = atomicAdd(&g_cnt[bvm],1); if (p < CAP2) lst[p] = make_float2(__int_as_float(n0 + 3*RED), v.w); }
    }
}

__global__ void __launch_bounds__(256, 6) fused_kernel(
        const float* __restrict__ feat,  const float* __restrict__ neigh,
        const float* __restrict__ emb,   const float* __restrict__ W_v,
        const float* __restrict__ b_v,   const float* __restrict__ W_edge,
        const float* __restrict__ W_r,   const float* __restrict__ b_r,
        const float* __restrict__ W_alpha, const float* __restrict__ b_alpha,
        const float* __restrict__ W_beta,  const float* __restrict__ b_beta) {
    __shared__ float4 s_a[TILE][HID/4];            // 8 KB (precompute); reused views below
    float* s_dot = (float*)&s_a[0][0];             // [MF]
    float* s_fs  = (float*)&s_a[1][0];             // [MF]

    const int bid = blockIdx.x;
    const int tid = threadIdx.x;

    if (bid < NBV) {
        // ---------------- role A: per-(b,v) attention + feat row sums ----------
        const int bv   = bid;
        const int warp = tid >> 5;
        const int lane = tid & 31;

        for (int m = warp; m < MF; m += 8) {
            const float4* fp = (const float4*)(feat + ((size_t)bv * MF + m) * NF);
            const float4* wa = (const float4*)W_alpha;
            float d0=0.f,d1=0.f, f0=0.f,f1=0.f;
            int i = lane;
            for (; i + 32 < NF4; i += 64) {
                float4 a0 = __ldcs(fp + i);
                float4 a1 = __ldcs(fp + i + 32);
                float4 w0 = __ldg(wa + i);
                float4 w1 = __ldg(wa + i + 32);
                d0 += a0.x*w0.x + a0.y*w0.y + a0.z*w0.z + a0.w*w0.w;
                d1 += a1.x*w1.x + a1.y*w1.y + a1.z*w1.z + a1.w*w1.w;
                f0 += a0.x + a0.y + a0.z + a0.w;
                f1 += a1.x + a1.y + a1.z + a1.w;
            }
            for (; i < NF4; i += 32) {
                float4 a = __ldcs(fp + i);
                float4 w = __ldg(wa + i);
                d0 += a.x*w.x + a.y*w.y + a.z*w.z + a.w*w.w;
                f0 += a.x + a.y + a.z + a.w;
            }
            float dot = d0 + d1;
            float fs  = f0 + f1;
            #pragma unroll
            for (int o = 16; o > 0; o >>= 1) {
                dot += __shfl_down_sync(0xffffffffu, dot, o);
                fs  += __shfl_down_sync(0xffffffffu, fs,  o);
            }
            if (lane == 0) { s_dot[m] = dot; s_fs[m] = fs; }
        }
        __syncthreads();

        if (tid == 0) {
            const int v = bv % NV;
            float lg[MF];
            float mx = -1e30f;
            #pragma unroll
            for (int m = 0; m < MF; m++) {
                lg[m] = s_dot[m] + __ldg(&b_alpha[m]);
                mx = fmaxf(mx, lg[m]);
            }
            float sum = 0.f;
            #pragma unroll
            for (int m = 0; m < MF; m++) { lg[m] = expf(lg[m] - mx); sum += lg[m]; }
            const float inv = 1.f / sum;
            float bl = __ldg(&b_beta[v]);
            #pragma unroll
            for (int m = 0; m < MF; m++) { lg[m] *= inv; bl += __ldg(&W_beta[m]) * lg[m]; }
            const float lamb = expf(-0.1f * (float)(NV - v));   // GAMMA=0.1
            const float beta = tanhf(bl) * lamb;
            #pragma unroll
            for (int m = 0; m < MF; m++) {
                g_attn[bv*MF + m] = lg[m] * beta;
                g_fsum[bv*MF + m] = s_fs[m];
            }
        }
    } else if (bid < ROLE0) {
        // ---------------- role B: reduced node/edge tables (tiled GEMM) --------
        const int pb = bid - NBV;
        const int r  = tid;

        const float* src; const float* Wp; const float* bp; float* outp;
        int row0, nrow;
        if (pb < 125) {
            row0 = pb * TILE; nrow = min(TILE, NF - row0);
            src = emb; Wp = W_v; bp = b_v; outp = g_red_emb;
        } else {
            row0 = 0; nrow = NR;
            src = W_edge; Wp = W_r; bp = b_r; outp = g_red_edge;
        }

        for (int idx = r; idx < nrow * (HID/4); idx += 256) {
            int t = idx >> 5, k = idx & 31;
            s_a[t][k] = ((const float4*)(src + (size_t)(row0 + t) * HID))[k];
        }
        __syncthreads();

        // two half-tiles of 8 accumulators each keeps register pressure <= 42
        const float4* w4 = (const float4*)(Wp + (size_t)r * HID);
        const float bias = __ldg(&bp[r]);
        #pragma unroll
        for (int half = 0; half < 2; half++) {
            float acc[TILE/2];
            #pragma unroll
            for (int t = 0; t < TILE/2; t++) acc[t] = 0.f;
            #pragma unroll 8
            for (int k = 0; k < HID/4; k++) {
                float4 w = __ldg(&w4[k]);
                #pragma unroll
                for (int t = 0; t < TILE/2; t++) {
                    float4 a = s_a[half*(TILE/2) + t][k];
                    acc[t] += a.x*w.x + a.y*w.y + a.z*w.z + a.w*w.w;
                }
            }
            const int hb = half * (TILE/2);
            for (int t = 0; t < TILE/2 && hb + t < nrow; t++)
                outp[(row0 + hb + t) * RED + r] = acc[t] + bias;
        }
    } else {
        // ---------------- role C: 293 MB stream -> sparse compaction -----------
        const float4* np = (const float4*)neigh;
        const int stride = (GRID1 - ROLE0) * 256;
        int i = (bid - ROLE0) * 256 + tid;
        for (; i + 7*stride < TOT4; i += 8*stride) {
            float4 v0 = __ldcs(np + i);
            float4 v1 = __ldcs(np + i + 1*stride);
            float4 v2 = __ldcs(np + i + 2*stride);
            float4 v3 = __ldcs(np + i + 3*stride);
            float4 v4 = __ldcs(np + i + 4*stride);
            float4 v5 = __ldcs(np + i + 5*stride);
            float4 v6 = __ldcs(np + i + 6*stride);
            float4 v7 = __ldcs(np + i + 7*stride);
            push_nz(v0, i);
            push_nz(v1, i + 1*stride);
            push_nz(v2, i + 2*stride);
            push_nz(v3, i + 3*stride);
            push_nz(v4, i + 4*stride);
            push_nz(v5, i + 5*stride);
            push_nz(v6, i + 6*stride);
            push_nz(v7, i + 7*stride);
        }
        for (; i < TOT4; i += stride)
            push_nz(__ldcs(np + i), i);
    }
}

// ---------------- kernel 2: sparse expansion + epilogue + batch accumulation --
// grid = 2304 (b,v,m), block = 256 (thread r owns reduced-dim column r)
__global__ void __launch_bounds__(256) expand_kernel(const float* __restrict__ rel,
                                                     const float* __restrict__ W_l,
                                                     const float* __restrict__ b_l) {
    __shared__ float2 s_list[CAP2];   // 4 KB
    __shared__ float  s_rel[NR];

    const int bid = blockIdx.x;
    const int tid = threadIdx.x;

    const int cnt = min(g_cnt[bid], CAP2);
    for (int j = tid; j < cnt; j += 256)
        s_list[j] = g_list[bid * CAP2 + j];

    if (tid < NR) {
        const float* rp = rel + (size_t)bid * (MT*NR) + tid;
        float e = 0.f;
        #pragma unroll
        for (int t = 0; t < MT; t++) e += __ldg(rp + t*NR);
        s_rel[tid] = e;
    }
    __syncthreads();

    // gather-weighted sum of reduced_emb rows; 8 independent L2 loads in flight
    const float* table = g_red_emb + tid;     // entries store pre-scaled n*RED
    float acc = 0.f;
    int j = 0;
    for (; j + 8 <= cnt; j += 8) {
        float2 e0 = s_list[j],   e1 = s_list[j+1], e2 = s_list[j+2], e3 = s_list[j+3];
        float2 e4 = s_list[j+4], e5 = s_list[j+5], e6 = s_list[j+6], e7 = s_list[j+7];
        float a0 = __ldg(table + __float_as_int(e0.x));
        float a1 = __ldg(table + __float_as_int(e1.x));
        float a2 = __ldg(table + __float_as_int(e2.x));
        float a3 = __ldg(table + __float_as_int(e3.x));
        float a4 = __ldg(table + __float_as_int(e4.x));
        float a5 = __ldg(table + __float_as_int(e5.x));
        float a6 = __ldg(table + __float_as_int(e6.x));
        float a7 = __ldg(table + __float_as_int(e7.x));
        acc += e0.y*a0 + e1.y*a1 + e2.y*a2 + e3.y*a3
             + e4.y*a4 + e5.y*a5 + e6.y*a6 + e7.y*a7;
    }
    for (; j < cnt; j++) {
        float2 e0 = s_list[j];
        acc += e0.y * __ldg(table + __float_as_int(e0.x));
    }

    // epilogue: agg = attn*node + edge ; h = relu(diag(W_l)*agg + b_l)
    const float a = __ldg(&g_attn[bid]);
    float edge = 0.f;
    #pragma unroll
    for (int e = 0; e < NR; e++) edge += s_rel[e] * __ldg(&g_red_edge[e*RED + tid]);
    const float agg = a * acc + edge;
    float h = __ldg(&W_l[tid * RED + tid]) * agg + __ldg(&b_l[tid]);
    h = fmaxf(h, 0.f);

    // accumulate batch-level reductions directly (72 contributors per address)
    const int b = bid / (NV*MF);
    atomicAdd(&g_hg[b*RED + tid], h);
    atomicAdd(&g_hp[b*RED + tid], __ldg(&g_fsum[bid]) * h);
}

// ---------------- kernel 3: FC + sigmoid + state reset for next replay --------
// grid = 32 (batch), block = 256
__global__ void final_kernel(const float* __restrict__ fc_W,
                             const float* __restrict__ fc_b,
                             float* __restrict__ out) {
    __shared__ float z[2*RED];
    const int b = blockIdx.x;
    const int r = threadIdx.x;

    z[r]       = g_hg[b*RED + r];
    z[RED + r] = g_hp[b*RED + r];
    // reset mutable state so the next graph replay starts clean
    g_hg[b*RED + r] = 0.f;
    g_hp[b*RED + r] = 0.f;
    {
        int gid = b * 256 + r;                 // 8192 threads cover 2304 counters
        if (gid < NBVM) g_cnt[gid] = 0;
    }
    __syncthreads();

    if (r < OUTD) {
        const float* w = fc_W + r * (2*RED);
        float a0 = 0.f, a1 = 0.f, a2 = 0.f, a3 = 0.f;
        #pragma unroll 4
        for (int k = 0; k < 2*RED; k += 4) {
            a0 += z[k]   * __ldg(&w[k]);
            a1 += z[k+1] * __ldg(&w[k+1]);
            a2 += z[k+2] * __ldg(&w[k+2]);
            a3 += z[k+3] * __ldg(&w[k+3]);
        }
        float acc = __ldg(&fc_b[r]) + ((a0 + a1) + (a2 + a3));
        out[b*OUTD + r] = 1.f / (1.f + expf(-acc));
    }
}

// ---------------- launcher ----------------
extern "C" void kernel_launch(void* const* d_in, const int* in_sizes, int n_in,
                              void* d_out, int out_size) {
    const float* feat    = (const float*)d_in[0];
    const float* neigh   = (const float*)d_in[1];
    const float* rel     = (const float*)d_in[2];
    const float* emb     = (const float*)d_in[3];
    const float* W_edge  = (const float*)d_in[4];
    const float* W_v     = (const float*)d_in[5];
    const float* W_r     = (const float*)d_in[6];
    const float* b_v     = (const float*)d_in[7];
    const float* b_r     = (const float*)d_in[8];
    const float* W_alpha = (const float*)d_in[9];
    const float* b_alpha = (const float*)d_in[10];
    const float* W_beta  = (const float*)d_in[11];
    const float* b_beta  = (const float*)d_in[12];
    const float* W_l     = (const float*)d_in[13];
    const float* b_l     = (const float*)d_in[14];
    const float* fc_W    = (const float*)d_in[15];
    const float* fc_b    = (const float*)d_in[16];
    float* out = (float*)d_out;

    fused_kernel<<<GRID1, 256>>>(feat, neigh, emb, W_v, b_v, W_edge, W_r, b_r,
                                 W_alpha, b_alpha, W_beta, b_beta);
    expand_kernel<<<NBVM, 256>>>(rel, W_l, b_l);
    final_kernel<<<BS, RED>>>(fc_W, fc_b, out);
}

// round 9
// speedup vs baseline: 1.6437x; 1.0088x over previous
#include <cuda_runtime.h>
#include <math.h>

#define BS   32
#define NV   6
#define MF   12
#define MT   16
#define NF   1992
#define NR   11
#define HID  128
#define RED  256
#define OUTD 90

#define NBV   (BS*NV)        // 192
#define NBVM  (BS*NV*MF)     // 2304
#define NF4   (NF/4)         // 498
#define I4TOT (MT*NF4)       // 7968 float4 per (b,v,m)
#define TOT4  (NBVM*I4TOT)   // 18,358,272 float4 total
#define CAP2  512            // nonzeros per (b,v,m); mean ~32 => hugely safe
#define SCAP  256            // smem-staged list entries (covers cnt<=256; tail reads global)

#define TILE  16
#define NPRE  126            // 125 emb-tile blocks + 1 edge block
#define ROLE0 (NBV + NPRE)   // 318: first compact block
#define NCOMPACT 2048
#define GRID1 (ROLE0 + NCOMPACT)

// ---------------- device scratch (no allocations; zero-init for first run; ----
// ---------------- final_kernel re-zeroes mutable state for graph replays) -----
__device__ float  g_red_emb[NF*RED];     // 2.04 MB node table (L2-resident)
__device__ float  g_red_edge[NR*RED];
__device__ float  g_attn[NBVM];
__device__ float  g_fsum[NBVM];
__device__ int    g_cnt[NBVM];           // per-(b,v,m) nonzero counters
__device__ float2 g_list[NBVM*CAP2];     // {bitcast(n*RED), value}
__device__ float  g_hg[BS*RED];          // h.sum(v,m)
__device__ float  g_hp[BS*RED];          // fsum-weighted h sum

// ---------------- fused kernel 1: attn | precompute | compact (independent) ---
__device__ __forceinline__ void push_nz(float4 v, int i) {
    if (v.x != 0.f || v.y != 0.f || v.z != 0.f || v.w != 0.f) {
        const int bvm  = i / I4TOT;
        const int rem4 = i - bvm * I4TOT;
        const int n0   = (rem4 % NF4) * (4*RED);   // pre-scaled row offset
        float2* lst = g_list + bvm * CAP2;
        if (v.x != 0.f) { int p = atomicAdd(&g_cnt[bvm],1); if (p < CAP2) lst[p] = make_float2(__int_as_float(n0        ), v.x); }
        if (v.y != 0.f) { int p = atomicAdd(&g_cnt[bvm],1); if (p < CAP2) lst[p] = make_float2(__int_as_float(n0 +   RED), v.y); }
        if (v.z != 0.f) { int p = atomicAdd(&g_cnt[bvm],1); if (p < CAP2) lst[p] = make_float2(__int_as_float(n0 + 2*RED), v.z); }
        if (v.w != 0.f) { int p = atomicAdd(&g_cnt[bvm],1); if (p < CAP2) lst[p] = make_float2(__int_as_float(n0 + 3*RED), v.w); }
    }
}

__global__ void __launch_bounds__(256) fused_kernel(
        const float* __restrict__ feat,  const float* __restrict__ neigh,
        const float* __restrict__ emb,   const float* __restrict__ W_v,
        const float* __restrict__ b_v,   const float* __restrict__ W_edge,
        const float* __restrict__ W_r,   const float* __restrict__ b_r,
        const float* __restrict__ W_alpha, const float* __restrict__ b_alpha,
        const float* __restrict__ W_beta,  const float* __restrict__ b_beta) {
    __shared__ float4 s_a[TILE][HID/4];            // 8 KB (precompute); reused views below
    float* s_dot = (float*)&s_a[0][0];             // [MF]
    float* s_fs  = (float*)&s_a[1][0];             // [MF]

    const int bid = blockIdx.x;
    const int tid = threadIdx.x;

    if (bid < NBV) {
        // ---------------- role A: per-(b,v) attention + feat row sums ----------
        const int bv   = bid;
        const int warp = tid >> 5;
        const int lane = tid & 31;

        for (int m = warp; m < MF; m += 8) {
            const float4* fp = (const float4*)(feat + ((size_t)bv * MF + m) * NF);
            const float4* wa = (const float4*)W_alpha;
            float d0=0.f,d1=0.f,d2=0.f,d3=0.f, f0=0.f,f1=0.f,f2=0.f,f3=0.f;
            int i = lane;
            for (; i + 96 < NF4; i += 128) {
                float4 a0 = __ldcs(fp + i);
                float4 a1 = __ldcs(fp + i + 32);
                float4 a2 = __ldcs(fp + i + 64);
                float4 a3 = __ldcs(fp + i + 96);
                float4 w0 = __ldg(wa + i);
                float4 w1 = __ldg(wa + i + 32);
                float4 w2 = __ldg(wa + i + 64);
                float4 w3 = __ldg(wa + i + 96);
                d0 += a0.x*w0.x + a0.y*w0.y + a0.z*w0.z + a0.w*w0.w;
                d1 += a1.x*w1.x + a1.y*w1.y + a1.z*w1.z + a1.w*w1.w;
                d2 += a2.x*w2.x + a2.y*w2.y + a2.z*w2.z + a2.w*w2.w;
                d3 += a3.x*w3.x + a3.y*w3.y + a3.z*w3.z + a3.w*w3.w;
                f0 += a0.x + a0.y + a0.z + a0.w;
                f1 += a1.x + a1.y + a1.z + a1.w;
                f2 += a2.x + a2.y + a2.z + a2.w;
                f3 += a3.x + a3.y + a3.z + a3.w;
            }
            for (; i < NF4; i += 32) {
                float4 a = __ldcs(fp + i);
                float4 w = __ldg(wa + i);
                d0 += a.x*w.x + a.y*w.y + a.z*w.z + a.w*w.w;
                f0 += a.x + a.y + a.z + a.w;
            }
            float dot = (d0 + d1) + (d2 + d3);
            float fs  = (f0 + f1) + (f2 + f3);
            #pragma unroll
            for (int o = 16; o > 0; o >>= 1) {
                dot += __shfl_down_sync(0xffffffffu, dot, o);
                fs  += __shfl_down_sync(0xffffffffu, fs,  o);
            }
            if (lane == 0) { s_dot[m] = dot; s_fs[m] = fs; }
        }
        __syncthreads();

        if (tid == 0) {
            const int v = bv % NV;
            float lg[MF];
            float mx = -1e30f;
            #pragma unroll
            for (int m = 0; m < MF; m++) {
                lg[m] = s_dot[m] + __ldg(&b_alpha[m]);
                mx = fmaxf(mx, lg[m]);
            }
            float sum = 0.f;
            #pragma unroll
            for (int m = 0; m < MF; m++) { lg[m] = expf(lg[m] - mx); sum += lg[m]; }
            const float inv = 1.f / sum;
            float bl = __ldg(&b_beta[v]);
            #pragma unroll
            for (int m = 0; m < MF; m++) { lg[m] *= inv; bl += __ldg(&W_beta[m]) * lg[m]; }
            const float lamb = expf(-0.1f * (float)(NV - v));   // GAMMA=0.1
            const float beta = tanhf(bl) * lamb;
            #pragma unroll
            for (int m = 0; m < MF; m++) {
                g_attn[bv*MF + m] = lg[m] * beta;
                g_fsum[bv*MF + m] = s_fs[m];
            }
        }
    } else if (bid < ROLE0) {
        // ---------------- role B: reduced node/edge tables (tiled GEMM) --------
        const int pb = bid - NBV;
        const int r  = tid;

        const float* src; const float* Wp; const float* bp; float* outp;
        int row0, nrow;
        if (pb < 125) {
            row0 = pb * TILE; nrow = min(TILE, NF - row0);
            src = emb; Wp = W_v; bp = b_v; outp = g_red_emb;
        } else {
            row0 = 0; nrow = NR;
            src = W_edge; Wp = W_r; bp = b_r; outp = g_red_edge;
        }

        for (int idx = r; idx < nrow * (HID/4); idx += 256) {
            int t = idx >> 5, k = idx & 31;
            s_a[t][k] = ((const float4*)(src + (size_t)(row0 + t) * HID))[k];
        }
        __syncthreads();

        float acc[TILE];
        #pragma unroll
        for (int t = 0; t < TILE; t++) acc[t] = 0.f;

        const float4* w4 = (const float4*)(Wp + (size_t)r * HID);
        #pragma unroll 8
        for (int k = 0; k < HID/4; k++) {
            float4 w = __ldg(&w4[k]);
            #pragma unroll
            for (int t = 0; t < TILE; t++) {
                float4 a = s_a[t][k];
                acc[t] += a.x*w.x + a.y*w.y + a.z*w.z + a.w*w.w;
            }
        }
        const float bias = __ldg(&bp[r]);
        for (int t = 0; t < nrow; t++)
            outp[(row0 + t) * RED + r] = acc[t] + bias;
    } else {
        // ---------------- role C: 293 MB stream -> sparse compaction -----------
        const float4* np = (const float4*)neigh;
        const int stride = (GRID1 - ROLE0) * 256;
        int i = (bid - ROLE0) * 256 + tid;
        for (; i + 7*stride < TOT4; i += 8*stride) {
            float4 v0 = __ldcs(np + i);
            float4 v1 = __ldcs(np + i + 1*stride);
            float4 v2 = __ldcs(np + i + 2*stride);
            float4 v3 = __ldcs(np + i + 3*stride);
            float4 v4 = __ldcs(np + i + 4*stride);
            float4 v5 = __ldcs(np + i + 5*stride);
            float4 v6 = __ldcs(np + i + 6*stride);
            float4 v7 = __ldcs(np + i + 7*stride);
            push_nz(v0, i);
            push_nz(v1, i + 1*stride);
            push_nz(v2, i + 2*stride);
            push_nz(v3, i + 3*stride);
            push_nz(v4, i + 4*stride);
            push_nz(v5, i + 5*stride);
            push_nz(v6, i + 6*stride);
            push_nz(v7, i + 7*stride);
        }
        for (; i < TOT4; i += stride)
            push_nz(__ldcs(np + i), i);
    }
}

// ---------------- kernel 2: sparse expansion + epilogue + batch accumulation --
// grid = 2304 (b,v,m), block = 256 (thread r owns reduced-dim column r)
// Critical-path fix: speculative list load runs concurrently with the cnt load
// (one global round instead of two dependent ones, one sync instead of two).
__global__ void __launch_bounds__(256) expand_kernel(const float* __restrict__ rel,
                                                     const float* __restrict__ W_l,
                                                     const float* __restrict__ b_l) {
    __shared__ float2 s_list[SCAP];   // 2 KB
    __shared__ float  s_rel[NR];

    const int bid = blockIdx.x;
    const int tid = threadIdx.x;

    // all issued back-to-back, no dependencies between them:
    const int cnt = min(__ldg(&g_cnt[bid]), CAP2);      // uniform broadcast load
    s_list[tid] = __ldg(&g_list[bid * CAP2 + tid]);     // speculative (past-cnt unused)
    if (tid < NR) {
        const float* rp = rel + (size_t)bid * (MT*NR) + tid;
        float e = 0.f;
        #pragma unroll
        for (int t = 0; t < MT; t++) e += __ldg(rp + t*NR);
        s_rel[tid] = e;
    }
    __syncthreads();

    // gather-weighted sum of reduced_emb rows; 8 independent L2 loads in flight
    const float* table = g_red_emb + tid;     // entries store pre-scaled n*RED
    const int scnt = min(cnt, SCAP);
    float acc = 0.f;
    int j = 0;
    for (; j + 8 <= scnt; j += 8) {
        float2 e0 = s_list[j],   e1 = s_list[j+1], e2 = s_list[j+2], e3 = s_list[j+3];
        float2 e4 = s_list[j+4], e5 = s_list[j+5], e6 = s_list[j+6], e7 = s_list[j+7];
        float a0 = __ldg(table + __float_as_int(e0.x));
        float a1 = __ldg(table + __float_as_int(e1.x));
        float a2 = __ldg(table + __float_as_int(e2.x));
        float a3 = __ldg(table + __float_as_int(e3.x));
        float a4 = __ldg(table + __float_as_int(e4.x));
        float a5 = __ldg(table + __float_as_int(e5.x));
        float a6 = __ldg(table + __float_as_int(e6.x));
        float a7 = __ldg(table + __float_as_int(e7.x));
        acc += e0.y*a0 + e1.y*a1 + e2.y*a2 + e3.y*a3
             + e4.y*a4 + e5.y*a5 + e6.y*a6 + e7.y*a7;
    }
    for (; j < scnt; j++) {
        float2 e0 = s_list[j];
        acc += e0.y * __ldg(table + __float_as_int(e0.x));
    }
    for (; j < cnt; j++) {                       // rare overflow tail: read global
        float2 e0 = __ldg(&g_list[bid * CAP2 + j]);
        acc += e0.y * __ldg(table + __float_as_int(e0.x));
    }

    // epilogue: agg = attn*node + edge ; h = relu(diag(W_l)*agg + b_l)
    const float a = __ldg(&g_attn[bid]);
    float edge = 0.f;
    #pragma unroll
    for (int e = 0; e < NR; e++) edge += s_rel[e] * __ldg(&g_red_edge[e*RED + tid]);
    const float agg = a * acc + edge;
    float h = __ldg(&W_l[tid * RED + tid]) * agg + __ldg(&b_l[tid]);
    h = fmaxf(h, 0.f);

    // accumulate batch-level reductions directly (72 contributors per address)
    const int b = bid / (NV*MF);
    atomicAdd(&g_hg[b*RED + tid], h);
    atomicAdd(&g_hp[b*RED + tid], __ldg(&g_fsum[bid]) * h);
}

// ---------------- kernel 3: FC + sigmoid + state reset for next replay --------
// grid = 32 (batch), block = 256
__global__ void final_kernel(const float* __restrict__ fc_W,
                             const float* __restrict__ fc_b,
                             float* __restrict__ out) {
    __shared__ float z[2*RED];
    const int b = blockIdx.x;
    const int r = threadIdx.x;

    z[r]       = g_hg[b*RED + r];
    z[RED + r] = g_hp[b*RED + r];
    // reset mutable state so the next graph replay starts clean
    g_hg[b*RED + r] = 0.f;
    g_hp[b*RED + r] = 0.f;
    {
        int gid = b * 256 + r;                 // 8192 threads cover 2304 counters
        if (gid < NBVM) g_cnt[gid] = 0;
    }
    __syncthreads();

    if (r < OUTD) {
        const float* w = fc_W + r * (2*RED);
        float a0 = 0.f, a1 = 0.f, a2 = 0.f, a3 = 0.f;
        #pragma unroll 4
        for (int k = 0; k < 2*RED; k += 4) {
            a0 += z[k]   * __ldg(&w[k]);
            a1 += z[k+1] * __ldg(&w[k+1]);
            a2 += z[k+2] * __ldg(&w[k+2]);
            a3 += z[k+3] * __ldg(&w[k+3]);
        }
        float acc = __ldg(&fc_b[r]) + ((a0 + a1) + (a2 + a3));
        out[b*OUTD + r] = 1.f / (1.f + expf(-acc));
    }
}

// ---------------- launcher ----------------
extern "C" void kernel_launch(void* const* d_in, const int* in_sizes, int n_in,
                              void* d_out, int out_size) {
    const float* feat    = (const float*)d_in[0];
    const float* neigh   = (const float*)d_in[1];
    const float* rel     = (const float*)d_in[2];
    const float* emb     = (const float*)d_in[3];
    const float* W_edge  = (const float*)d_in[4];
    const float* W_v     = (const float*)d_in[5];
    const float* W_r     = (const float*)d_in[6];
    const float* b_v     = (const float*)d_in[7];
    const float* b_r     = (const float*)d_in[8];
    const float* W_alpha = (const float*)d_in[9];
    const float* b_alpha = (const float*)d_in[10];
    const float* W_beta  = (const float*)d_in[11];
    const float* b_beta  = (const float*)d_in[12];
    const float* W_l     = (const float*)d_in[13];
    const float* b_l     = (const float*)d_in[14];
    const float* fc_W    = (const float*)d_in[15];
    const float* fc_b    = (const float*)d_in[16];
    float* out = (float*)d_out;

    fused_kernel<<<GRID1, 256>>>(feat, neigh, emb, W_v, b_v, W_edge, W_r, b_r,
                                 W_alpha, b_alpha, W_beta, b_beta);
    expand_kernel<<<NBVM, 256>>>(rel, W_l, b_l);
    final_kernel<<<BS, RED>>>(fc_W, fc_b, out);
}

// round 10
// speedup vs baseline: 1.6588x; 1.0092x over previous
#include <cuda_runtime.h>
#include <math.h>

#define BS   32
#define NV   6
#define MF   12
#define MT   16
#define NF   1992
#define NR   11
#define HID  128
#define RED  256
#define OUTD 90

#define NBV   (BS*NV)        // 192
#define NBVM  (BS*NV*MF)     // 2304
#define NF4   (NF/4)         // 498
#define I4TOT (MT*NF4)       // 7968 float4 per (b,v,m)
#define TOT4  (NBVM*I4TOT)   // 18,358,272 float4 total
#define CAP2  512            // nonzeros per (b,v,m); mean ~32 => hugely safe
#define SCAP  256            // smem-staged list entries (covers cnt<=256; tail reads global)

#define TILE  16
#define NPRE  126            // 125 emb-tile blocks + 1 edge block
#define ROLE0 (NBV + NPRE)   // 318: first compact block
#define NCOMPACT 2048
#define GRID1 (ROLE0 + NCOMPACT)

// ---------------- device scratch (no allocations; zero-init for first run; ----
// ---------------- final_kernel re-zeroes mutable state for graph replays) -----
__device__ float  g_red_emb[NF*RED];     // 2.04 MB node table (L2-resident)
__device__ float  g_red_edge[NR*RED];
__device__ float  g_attn[NBVM];
__device__ float  g_fsum[NBVM];
__device__ int    g_cnt[NBVM];           // per-(b,v,m) nonzero counters
__device__ float2 g_list[NBVM*CAP2];     // {bitcast(n*64 float4-offset), value}
__device__ float  g_hg[BS*RED];          // h.sum(v,m)
__device__ float  g_hp[BS*RED];          // fsum-weighted h sum

// ---------------- fused kernel 1: attn | precompute | compact (independent) ---
__device__ __forceinline__ void push_nz(float4 v, int i) {
    if (v.x != 0.f || v.y != 0.f || v.z != 0.f || v.w != 0.f) {
        const int bvm  = i / I4TOT;
        const int rem4 = i - bvm * I4TOT;
        const int n0   = (rem4 % NF4) << 8;        // (n/4)*4 rows * 64 float4/row
        float2* lst = g_list + bvm * CAP2;
        if (v.x != 0.f) { int p = atomicAdd(&g_cnt[bvm],1); if (p < CAP2) lst[p] = make_float2(__int_as_float(n0      ), v.x); }
        if (v.y != 0.f) { int p = atomicAdd(&g_cnt[bvm],1); if (p < CAP2) lst[p] = make_float2(__int_as_float(n0 +  64), v.y); }
        if (v.z != 0.f) { int p = atomicAdd(&g_cnt[bvm],1); if (p < CAP2) lst[p] = make_float2(__int_as_float(n0 + 128), v.z); }
        if (v.w != 0.f) { int p = atomicAdd(&g_cnt[bvm],1); if (p < CAP2) lst[p] = make_float2(__int_as_float(n0 + 192), v.w); }
    }
}

__global__ void __launch_bounds__(256) fused_kernel(
        const float* __restrict__ feat,  const float* __restrict__ neigh,
        const float* __restrict__ emb,   const float* __restrict__ W_v,
        const float* __restrict__ b_v,   const float* __restrict__ W_edge,
        const float* __restrict__ W_r,   const float* __restrict__ b_r,
        const float* __restrict__ W_alpha, const float* __restrict__ b_alpha,
        const float* __restrict__ W_beta,  const float* __restrict__ b_beta) {
    __shared__ float4 s_a[TILE][HID/4];            // 8 KB (precompute); reused views below
    float* s_dot = (float*)&s_a[0][0];             // [MF]
    float* s_fs  = (float*)&s_a[1][0];             // [MF]

    const int bid = blockIdx.x;
    const int tid = threadIdx.x;

    if (bid < NBV) {
        // ---------------- role A: per-(b,v) attention + feat row sums ----------
        const int bv   = bid;
        const int warp = tid >> 5;
        const int lane = tid & 31;

        for (int m = warp; m < MF; m += 8) {
            const float4* fp = (const float4*)(feat + ((size_t)bv * MF + m) * NF);
            const float4* wa = (const float4*)W_alpha;
            float d0=0.f,d1=0.f,d2=0.f,d3=0.f, f0=0.f,f1=0.f,f2=0.f,f3=0.f;
            int i = lane;
            for (; i + 96 < NF4; i += 128) {
                float4 a0 = __ldcs(fp + i);
                float4 a1 = __ldcs(fp + i + 32);
                float4 a2 = __ldcs(fp + i + 64);
                float4 a3 = __ldcs(fp + i + 96);
                float4 w0 = __ldg(wa + i);
                float4 w1 = __ldg(wa + i + 32);
                float4 w2 = __ldg(wa + i + 64);
                float4 w3 = __ldg(wa + i + 96);
                d0 += a0.x*w0.x + a0.y*w0.y + a0.z*w0.z + a0.w*w0.w;
                d1 += a1.x*w1.x + a1.y*w1.y + a1.z*w1.z + a1.w*w1.w;
                d2 += a2.x*w2.x + a2.y*w2.y + a2.z*w2.z + a2.w*w2.w;
                d3 += a3.x*w3.x + a3.y*w3.y + a3.z*w3.z + a3.w*w3.w;
                f0 += a0.x + a0.y + a0.z + a0.w;
                f1 += a1.x + a1.y + a1.z + a1.w;
                f2 += a2.x + a2.y + a2.z + a2.w;
                f3 += a3.x + a3.y + a3.z + a3.w;
            }
            for (; i < NF4; i += 32) {
                float4 a = __ldcs(fp + i);
                float4 w = __ldg(wa + i);
                d0 += a.x*w.x + a.y*w.y + a.z*w.z + a.w*w.w;
                f0 += a.x + a.y + a.z + a.w;
            }
            float dot = (d0 + d1) + (d2 + d3);
            float fs  = (f0 + f1) + (f2 + f3);
            #pragma unroll
            for (int o = 16; o > 0; o >>= 1) {
                dot += __shfl_down_sync(0xffffffffu, dot, o);
                fs  += __shfl_down_sync(0xffffffffu, fs,  o);
            }
            if (lane == 0) { s_dot[m] = dot; s_fs[m] = fs; }
        }
        __syncthreads();

        if (tid == 0) {
            const int v = bv % NV;
            float lg[MF];
            float mx = -1e30f;
            #pragma unroll
            for (int m = 0; m < MF; m++) {
                lg[m] = s_dot[m] + __ldg(&b_alpha[m]);
                mx = fmaxf(mx, lg[m]);
            }
            float sum = 0.f;
            #pragma unroll
            for (int m = 0; m < MF; m++) { lg[m] = expf(lg[m] - mx); sum += lg[m]; }
            const float inv = 1.f / sum;
            float bl = __ldg(&b_beta[v]);
            #pragma unroll
            for (int m = 0; m < MF; m++) { lg[m] *= inv; bl += __ldg(&W_beta[m]) * lg[m]; }
            const float lamb = expf(-0.1f * (float)(NV - v));   // GAMMA=0.1
            const float beta = tanhf(bl) * lamb;
            #pragma unroll
            for (int m = 0; m < MF; m++) {
                g_attn[bv*MF + m] = lg[m] * beta;
                g_fsum[bv*MF + m] = s_fs[m];
            }
        }
    } else if (bid < ROLE0) {
        // ---------------- role B: reduced node/edge tables (tiled GEMM) --------
        const int pb = bid - NBV;
        const int r  = tid;

        const float* src; const float* Wp; const float* bp; float* outp;
        int row0, nrow;
        if (pb < 125) {
            row0 = pb * TILE; nrow = min(TILE, NF - row0);
            src = emb; Wp = W_v; bp = b_v; outp = g_red_emb;
        } else {
            row0 = 0; nrow = NR;
            src = W_edge; Wp = W_r; bp = b_r; outp = g_red_edge;
        }

        for (int idx = r; idx < nrow * (HID/4); idx += 256) {
            int t = idx >> 5, k = idx & 31;
            s_a[t][k] = ((const float4*)(src + (size_t)(row0 + t) * HID))[k];
        }
        __syncthreads();

        float acc[TILE];
        #pragma unroll
        for (int t = 0; t < TILE; t++) acc[t] = 0.f;

        const float4* w4 = (const float4*)(Wp + (size_t)r * HID);
        #pragma unroll 8
        for (int k = 0; k < HID/4; k++) {
            float4 w = __ldg(&w4[k]);
            #pragma unroll
            for (int t = 0; t < TILE; t++) {
                float4 a = s_a[t][k];
                acc[t] += a.x*w.x + a.y*w.y + a.z*w.z + a.w*w.w;
            }
        }
        const float bias = __ldg(&bp[r]);
        for (int t = 0; t < nrow; t++)
            outp[(row0 + t) * RED + r] = acc[t] + bias;
    } else {
        // ---------------- role C: 293 MB stream -> sparse compaction -----------
        const float4* np = (const float4*)neigh;
        const int stride = (GRID1 - ROLE0) * 256;
        int i = (bid - ROLE0) * 256 + tid;
        for (; i + 7*stride < TOT4; i += 8*stride) {
            float4 v0 = __ldcs(np + i);
            float4 v1 = __ldcs(np + i + 1*stride);
            float4 v2 = __ldcs(np + i + 2*stride);
            float4 v3 = __ldcs(np + i + 3*stride);
            float4 v4 = __ldcs(np + i + 4*stride);
            float4 v5 = __ldcs(np + i + 5*stride);
            float4 v6 = __ldcs(np + i + 6*stride);
            float4 v7 = __ldcs(np + i + 7*stride);
            push_nz(v0, i);
            push_nz(v1, i + 1*stride);
            push_nz(v2, i + 2*stride);
            push_nz(v3, i + 3*stride);
            push_nz(v4, i + 4*stride);
            push_nz(v5, i + 5*stride);
            push_nz(v6, i + 6*stride);
            push_nz(v7, i + 7*stride);
        }
        for (; i < TOT4; i += stride)
            push_nz(__ldcs(np + i), i);
    }
}

// ---------------- kernel 2: sparse expansion (float4 gathers) + epilogue ------
// grid = 2304 (b,v,m), block = 256.
// Gather layout: eg = tid>>6 picks every-4th entry, c4 = tid&63 picks 4 columns.
// Each thread does float4 gathers (16B) instead of 4B scalars: LDG & ALU /4.
__global__ void __launch_bounds__(256) expand_kernel(const float* __restrict__ rel,
                                                     const float* __restrict__ W_l,
                                                     const float* __restrict__ b_l) {
    __shared__ float2 s_list[SCAP];   // 2 KB
    __shared__ float4 s_red[256];     // 4 KB cross-entry-group reduction
    __shared__ float  s_rel[NR];

    const int bid = blockIdx.x;
    const int tid = threadIdx.x;
    const int eg  = tid >> 6;         // 0..3 entry group
    const int c4  = tid & 63;         // float4 column group

    // issued back-to-back, no dependencies between the loads:
    const int cnt = min(__ldg(&g_cnt[bid]), CAP2);      // uniform broadcast load
    float2 spec = __ldg(&g_list[bid * CAP2 + tid]);     // speculative (past-cnt unused)
    if (tid < NR) {
        const float* rp = rel + (size_t)bid * (MT*NR) + tid;
        float e = 0.f;
        #pragma unroll
        for (int t = 0; t < MT; t++) e += __ldg(rp + t*NR);
        s_rel[tid] = e;
    }
    s_list[tid] = (tid < cnt) ? spec : make_float2(__int_as_float(0), 0.f);
    __syncthreads();

    const int scnt  = min(cnt, SCAP);
    const int scnt4 = (scnt + 3) & ~3;                  // padded entries have w=0
    const float4* tab4 = ((const float4*)g_red_emb) + c4;

    float4 acc4 = make_float4(0.f, 0.f, 0.f, 0.f);
    int j = eg;
    for (; j + 12 < scnt4; j += 16) {                   // 4 independent 16B gathers
        float2 e0 = s_list[j], e1 = s_list[j+4], e2 = s_list[j+8], e3 = s_list[j+12];
        float4 t0 = __ldg(tab4 + __float_as_int(e0.x));
        float4 t1 = __ldg(tab4 + __float_as_int(e1.x));
        float4 t2 = __ldg(tab4 + __float_as_int(e2.x));
        float4 t3 = __ldg(tab4 + __float_as_int(e3.x));
        acc4.x += e0.y*t0.x + e1.y*t1.x + e2.y*t2.x + e3.y*t3.x;
        acc4.y += e0.y*t0.y + e1.y*t1.y + e2.y*t2.y + e3.y*t3.y;
        acc4.z += e0.y*t0.z + e1.y*t1.z + e2.y*t2.z + e3.y*t3.z;
        acc4.w += e0.y*t0.w + e1.y*t1.w + e2.y*t2.w + e3.y*t3.w;
    }
    for (; j < scnt4; j += 4) {
        float2 e0 = s_list[j];
        float4 t0 = __ldg(tab4 + __float_as_int(e0.x));
        acc4.x += e0.y*t0.x; acc4.y += e0.y*t0.y;
        acc4.z += e0.y*t0.z; acc4.w += e0.y*t0.w;
    }
    for (j = SCAP + eg; j < cnt; j += 4) {              // rare overflow tail
        float2 e0 = __ldg(&g_list[bid * CAP2 + j]);
        float4 t0 = __ldg(tab4 + __float_as_int(e0.x));
        acc4.x += e0.y*t0.x; acc4.y += e0.y*t0.y;
        acc4.z += e0.y*t0.z; acc4.w += e0.y*t0.w;
    }

    s_red[eg * 64 + c4] = acc4;
    __syncthreads();

    // thread r re-forms the full sum for column r (word addrs consecutive in r)
    const float* sr = (const float*)s_red;
    float acc = sr[tid] + sr[256 + tid] + sr[512 + tid] + sr[768 + tid];

    // epilogue: agg = attn*node + edge ; h = relu(diag(W_l)*agg + b_l)
    const float a = __ldg(&g_attn[bid]);
    float edge = 0.f;
    #pragma unroll
    for (int e = 0; e < NR; e++) edge += s_rel[e] * __ldg(&g_red_edge[e*RED + tid]);
    const float agg = a * acc + edge;
    float h = __ldg(&W_l[tid * RED + tid]) * agg + __ldg(&b_l[tid]);
    h = fmaxf(h, 0.f);

    // accumulate batch-level reductions directly (72 contributors per address)
    const int b = bid / (NV*MF);
    atomicAdd(&g_hg[b*RED + tid], h);
    atomicAdd(&g_hp[b*RED + tid], __ldg(&g_fsum[bid]) * h);
}

// ---------------- kernel 3: FC + sigmoid + state reset for next replay --------
// grid = 32 (batch), block = 256
__global__ void final_kernel(const float* __restrict__ fc_W,
                             const float* __restrict__ fc_b,
                             float* __restrict__ out) {
    __shared__ float z[2*RED];
    const int b = blockIdx.x;
    const int r = threadIdx.x;

    z[r]       = g_hg[b*RED + r];
    z[RED + r] = g_hp[b*RED + r];
    // reset mutable state so the next graph replay starts clean
    g_hg[b*RED + r] = 0.f;
    g_hp[b*RED + r] = 0.f;
    {
        int gid = b * 256 + r;                 // 8192 threads cover 2304 counters
        if (gid < NBVM) g_cnt[gid] = 0;
    }
    __syncthreads();

    if (r < OUTD) {
        const float* w = fc_W + r * (2*RED);
        float a0 = 0.f, a1 = 0.f, a2 = 0.f, a3 = 0.f;
        #pragma unroll 4
        for (int k = 0; k < 2*RED; k += 4) {
            a0 += z[k]   * __ldg(&w[k]);
            a1 += z[k+1] * __ldg(&w[k+1]);
            a2 += z[k+2] * __ldg(&w[k+2]);
            a3 += z[k+3] * __ldg(&w[k+3]);
        }
        float acc = __ldg(&fc_b[r]) + ((a0 + a1) + (a2 + a3));
        out[b*OUTD + r] = 1.f / (1.f + expf(-acc));
    }
}

// ---------------- launcher ----------------
extern "C" void kernel_launch(void* const* d_in, const int* in_sizes, int n_in,
                              void* d_out, int out_size) {
    const float* feat    = (const float*)d_in[0];
    const float* neigh   = (const float*)d_in[1];
    const float* rel     = (const float*)d_in[2];
    const float* emb     = (const float*)d_in[3];
    const float* W_edge  = (const float*)d_in[4];
    const float* W_v     = (const float*)d_in[5];
    const float* W_r     = (const float*)d_in[6];
    const float* b_v     = (const float*)d_in[7];
    const float* b_r     = (const float*)d_in[8];
    const float* W_alpha = (const float*)d_in[9];
    const float* b_alpha = (const float*)d_in[10];
    const float* W_beta  = (const float*)d_in[11];
    const float* b_beta  = (const float*)d_in[12];
    const float* W_l     = (const float*)d_in[13];
    const float* b_l     = (const float*)d_in[14];
    const float* fc_W    = (const float*)d_in[15];
    const float* fc_b    = (const float*)d_in[16];
    float* out = (float*)d_out;

    fused_kernel<<<GRID1, 256>>>(feat, neigh, emb, W_v, b_v, W_edge, W_r, b_r,
                                 W_alpha, b_alpha, W_beta, b_beta);
    expand_kernel<<<NBVM, 256>>>(rel, W_l, b_l);
    final_kernel<<<BS, RED>>>(fc_W, fc_b, out);
}